// round 1
// baseline (speedup 1.0000x reference)
#include <cuda_runtime.h>

#define BB 32
#define LL 2048
#define CC 512
#define QQ 512
#define HH 1024

// ---------------- scratch (no allocations allowed) ----------------
__device__ float g_resq[BB * HH];        // 128 KB
__device__ float g_logit[BB * LL];       // 256 KB
__device__ float g_weights[BB * LL];     // 256 KB
__device__ float g_part[BB * 8 * CC];    // 512 KB

// ---------------- kernel 1: res_q = query @ Wq^T  [32,1024] ----------------
__global__ void resq_kernel(const float* __restrict__ query,
                            const float* __restrict__ Wq) {
    __shared__ float q[QQ];
    const int b = blockIdx.x, t = threadIdx.x;
    for (int i = t; i < QQ; i += 256) q[i] = query[b * QQ + i];
    __syncthreads();
    #pragma unroll
    for (int j = 0; j < 4; j++) {
        const int h = t + j * 256;
        const float4* w = (const float4*)(Wq + (size_t)h * QQ);
        float acc = 0.f;
        #pragma unroll 8
        for (int c4 = 0; c4 < QQ / 4; c4++) {
            float4 wv = w[c4];
            acc += wv.x * q[c4 * 4 + 0] + wv.y * q[c4 * 4 + 1]
                 + wv.z * q[c4 * 4 + 2] + wv.w * q[c4 * 4 + 3];
        }
        g_resq[b * HH + h] = acc;
    }
}

// ---------------- kernel 2: fused GEMM + tanh + Wo-reduce -> logits ----------------
// Per CTA: 64 M-rows (one b, since 64 | 2048), full H=1024 in 8 N-tiles of 128,
// K=512 in chunks of 32. Micro-tile 4(m) x 8(n) per thread, 256 threads (16x16).
__global__ __launch_bounds__(256) void logits_kernel(
    const float* __restrict__ ctx, const float* __restrict__ Wc,
    const float* __restrict__ bc, const float* __restrict__ Wo,
    const float* __restrict__ bo) {
    __shared__ __align__(16) float As[32][65];    // [k][m], pad 1 -> conflict-free store
    __shared__ __align__(16) float Bs[32][132];   // [k][n], pad 4 -> 16B-aligned float4 reads
    __shared__ float rqs[128];                    // res_q + bc for this n-tile
    __shared__ float wos[128];                    // Wo for this n-tile
    __shared__ float red[16][64];

    const int t = threadIdx.x;
    const int tx = t & 15, ty = t >> 4;
    const int m_base = blockIdx.x * 64;
    const int b = m_base >> 11;   // L = 2048

    float part[4] = {0.f, 0.f, 0.f, 0.f};

    for (int nt = 0; nt < 8; nt++) {
        const int n_base = nt * 128;
        __syncthreads();   // previous epilogue done before rqs/wos rewrite
        if (t < 128) {
            rqs[t] = g_resq[b * HH + n_base + t] + bc[n_base + t];
            wos[t] = Wo[n_base + t];
        }
        float acc[4][8];
        #pragma unroll
        for (int i = 0; i < 4; i++)
            #pragma unroll
            for (int j = 0; j < 8; j++) acc[i][j] = 0.f;

        for (int kk = 0; kk < CC; kk += 32) {
            __syncthreads();
            // A tile: 64 x 32 (coalesced global, conflict-free transposed store)
            #pragma unroll
            for (int i = 0; i < 8; i++) {
                const int idx = t + i * 256;
                const int m = idx >> 5, k = idx & 31;
                As[k][m] = ctx[(size_t)(m_base + m) * CC + kk + k];
            }
            // B tile: 128 x 32
            #pragma unroll
            for (int i = 0; i < 16; i++) {
                const int idx = t + i * 256;
                const int n = idx >> 5, k = idx & 31;
                Bs[k][n] = Wc[(size_t)(n_base + n) * CC + kk + k];
            }
            __syncthreads();
            #pragma unroll
            for (int k = 0; k < 32; k++) {
                float av[4];
                av[0] = As[k][ty * 4 + 0];
                av[1] = As[k][ty * 4 + 1];
                av[2] = As[k][ty * 4 + 2];
                av[3] = As[k][ty * 4 + 3];
                const float4 b0 = *(const float4*)&Bs[k][tx * 4];
                const float4 b1 = *(const float4*)&Bs[k][64 + tx * 4];
                float bv[8] = {b0.x, b0.y, b0.z, b0.w, b1.x, b1.y, b1.z, b1.w};
                #pragma unroll
                for (int i = 0; i < 4; i++)
                    #pragma unroll
                    for (int j = 0; j < 8; j++) acc[i][j] += av[i] * bv[j];
            }
        }
        // epilogue: logit partials; n_local = (j>>2)*64 + tx*4 + (j&3)
        #pragma unroll
        for (int i = 0; i < 4; i++) {
            #pragma unroll
            for (int j = 0; j < 8; j++) {
                const int n = ((j >> 2) << 6) + tx * 4 + (j & 3);
                part[i] += wos[n] * tanhf(acc[i][j] + rqs[n]);
            }
        }
    }

    __syncthreads();
    #pragma unroll
    for (int i = 0; i < 4; i++) red[tx][ty * 4 + i] = part[i];
    __syncthreads();
    if (t < 64) {
        float s = bo[0];
        #pragma unroll
        for (int j = 0; j < 16; j++) s += red[j][t];
        g_logit[m_base + t] = s;
    }
}

// ---------------- kernel 3: masked exp + normalize over L ----------------
__global__ void softmax_kernel(const float* __restrict__ mask,
                               float* __restrict__ w_out, int write_w) {
    __shared__ float sred[256];
    const int b = blockIdx.x, t = threadIdx.x;
    float e[8];
    float s = 0.f;
    #pragma unroll
    for (int i = 0; i < 8; i++) {
        const int l = t + i * 256;
        const float ev = mask[b * LL + l] * expf(g_logit[b * LL + l]);
        e[i] = ev;
        s += ev;
    }
    sred[t] = s;
    __syncthreads();
    #pragma unroll
    for (int off = 128; off > 0; off >>= 1) {
        if (t < off) sred[t] += sred[t + off];
        __syncthreads();
    }
    const float inv = 1.f / (sred[0] + 1e-5f);
    #pragma unroll
    for (int i = 0; i < 8; i++) {
        const int l = t + i * 256;
        const float wv = e[i] * inv;
        g_weights[b * LL + l] = wv;
        if (write_w) w_out[b * LL + l] = wv;
    }
}

// ---------------- kernel 4: weighted sum over L (8-way split, deterministic) ----------------
__global__ void wsum_kernel(const float* __restrict__ ctx) {
    const int b = blockIdx.x, ls = blockIdx.y, t = threadIdx.x;
    __shared__ float ws[256];
    ws[t] = g_weights[b * LL + ls * 256 + t];
    __syncthreads();
    float a0 = 0.f, a1 = 0.f;
    const size_t base_l = (size_t)b * LL + ls * 256;
    #pragma unroll 4
    for (int li = 0; li < 256; li++) {
        const float w = ws[li];
        const float* row = ctx + (base_l + li) * CC;
        a0 += w * row[t];
        a1 += w * row[256 + t];
    }
    g_part[(size_t)(b * 8 + ls) * CC + t] = a0;
    g_part[(size_t)(b * 8 + ls) * CC + 256 + t] = a1;
}

__global__ void reduce_kernel(float* __restrict__ out_vec) {
    const int idx = blockIdx.x * 256 + threadIdx.x;  // 0..16383
    const int b = idx >> 9, c = idx & 511;
    float s = 0.f;
    #pragma unroll
    for (int ls = 0; ls < 8; ls++) s += g_part[(size_t)(b * 8 + ls) * CC + c];
    out_vec[b * CC + c] = s;
}

// ---------------- launch ----------------
extern "C" void kernel_launch(void* const* d_in, const int* in_sizes, int n_in,
                              void* d_out, int out_size) {
    const float* query   = (const float*)d_in[0];
    const float* context = (const float*)d_in[1];
    const float* mask    = (const float*)d_in[2];
    const float* Wq      = (const float*)d_in[3];
    const float* Wc      = (const float*)d_in[4];
    const float* bc      = (const float*)d_in[5];
    const float* Wo      = (const float*)d_in[6];
    const float* bo      = (const float*)d_in[7];

    float* out = (float*)d_out;
    float* out_vec = nullptr;
    float* out_w = nullptr;
    if (out_size >= BB * CC + BB * LL) {         // (output, weights) concatenated
        out_vec = out;
        out_w = out + BB * CC;
    } else if (out_size == BB * LL) {            // weights only
        out_w = out;
    } else {                                     // output only (or unknown): write vec
        out_vec = out;
    }

    resq_kernel<<<BB, 256>>>(query, Wq);
    logits_kernel<<<(BB * LL) / 64, 256>>>(context, Wc, bc, Wo, bo);
    softmax_kernel<<<BB, 256>>>(mask, out_w, out_w != nullptr ? 1 : 0);
    wsum_kernel<<<dim3(BB, 8), 256>>>(context);
    if (out_vec) reduce_kernel<<<(BB * CC) / 256, 256>>>(out_vec);
}

// round 3
// speedup vs baseline: 4.1915x; 4.1915x over previous
#include <cuda_runtime.h>
#include <cuda_fp16.h>
#include <cstdint>

#define BB 32
#define LL 2048
#define CC 512
#define QQ 512
#define HH 1024

// ---------------- scratch (no allocations allowed) ----------------
__device__ float g_resq[BB * HH];          // 128 KB
__device__ float g_logit[BB * LL];         // 256 KB
__device__ float g_weights[BB * LL];       // 256 KB
__device__ float g_part[BB * 32 * CC];     // 2 MB
__device__ __half g_wc_h[HH * CC];         // 1 MB  (Wc in fp16, [h][k])

// ---------------- helpers ----------------
__device__ __forceinline__ uint32_t smem_u32(const void* p) {
    uint32_t a;
    asm("{ .reg .u64 t; cvta.to.shared.u64 t, %1; cvt.u32.u64 %0, t; }"
        : "=r"(a) : "l"(p));
    return a;
}

__device__ __forceinline__ void ldsm4(uint32_t& r0, uint32_t& r1,
                                      uint32_t& r2, uint32_t& r3, uint32_t addr) {
    asm volatile("ldmatrix.sync.aligned.m8n8.x4.shared.b16 {%0,%1,%2,%3}, [%4];"
                 : "=r"(r0), "=r"(r1), "=r"(r2), "=r"(r3) : "r"(addr));
}

__device__ __forceinline__ void mma16816(float* c,
                                         uint32_t a0, uint32_t a1, uint32_t a2, uint32_t a3,
                                         uint32_t b0, uint32_t b1) {
    asm volatile(
        "mma.sync.aligned.m16n8k16.row.col.f32.f16.f16.f32 "
        "{%0,%1,%2,%3}, {%4,%5,%6,%7}, {%8,%9}, {%0,%1,%2,%3};"
        : "+f"(c[0]), "+f"(c[1]), "+f"(c[2]), "+f"(c[3])
        : "r"(a0), "r"(a1), "r"(a2), "r"(a3), "r"(b0), "r"(b1));
}

__device__ __forceinline__ void cp_async16(uint32_t dst, const void* src) {
    asm volatile("cp.async.cg.shared.global [%0], [%1], 16;" :: "r"(dst), "l"(src));
}
#define CP_COMMIT() asm volatile("cp.async.commit_group;" ::: "memory")
#define CP_WAIT(n)  asm volatile("cp.async.wait_group %0;" :: "n"(n) : "memory")

// FMA/ALU-only tanh (no MUFU): exp2 range reduction + deg-5 poly + bit-hack rcp.
// abs err ~1e-5. MUFU tanh/exp would bottleneck at ~0.5ms for the 67M evals.
__device__ __forceinline__ float tanh_fma(float x) {
    float z = 2.885390081777927f * x;                // 2x * log2(e)
    z = fminf(30.f, fmaxf(-30.f, z));
    float zm = z + 12582912.f;                       // 1.5*2^23 magic
    int nsh = __float_as_int(zm) << 23;              // n << 23 (exponent add)
    float f = z - (zm - 12582912.f);                 // f in [-0.5, 0.5]
    float p = 1.3333558146e-3f;
    p = fmaf(p, f, 9.6181291076e-3f);
    p = fmaf(p, f, 5.5504108665e-2f);
    p = fmaf(p, f, 2.4022650695e-1f);
    p = fmaf(p, f, 6.9314718056e-1f);
    p = fmaf(p, f, 1.0f);                            // 2^f
    float t = __int_as_float(__float_as_int(p) + nsh);  // e^{2x}
    float d = t + 1.0f;
    float y = __int_as_float(0x7EF311C3 - __float_as_int(d));  // ~1/d
    y = y * fmaf(-d, y, 2.0f);
    y = y * fmaf(-d, y, 2.0f);
    return fmaf(-2.0f, y, 1.0f);                     // 1 - 2/(e^{2x}+1)
}

// ---------------- kernel 0: Wc -> fp16 ----------------
__global__ void wcprep_kernel(const float* __restrict__ Wc) {
    const int i = blockIdx.x * 256 + threadIdx.x;    // 131072 float4s
    float4 v = reinterpret_cast<const float4*>(Wc)[i];
    __half2 h0 = __floats2half2_rn(v.x, v.y);
    __half2 h1 = __floats2half2_rn(v.z, v.w);
    uint2 u;
    u.x = *reinterpret_cast<uint32_t*>(&h0);
    u.y = *reinterpret_cast<uint32_t*>(&h1);
    reinterpret_cast<uint2*>(g_wc_h)[i] = u;
}

// ---------------- kernel 1: res_q = query @ Wq^T ----------------
__global__ void resq_kernel(const float* __restrict__ query,
                            const float* __restrict__ Wq) {
    __shared__ float q[QQ];
    const int b = blockIdx.x, t = threadIdx.x;
    for (int i = t; i < QQ; i += 256) q[i] = query[b * QQ + i];
    __syncthreads();
#pragma unroll
    for (int j = 0; j < 4; j++) {
        const int h = t + j * 256;
        const float4* w = (const float4*)(Wq + (size_t)h * QQ);
        float acc = 0.f;
#pragma unroll 8
        for (int c4 = 0; c4 < QQ / 4; c4++) {
            float4 wv = w[c4];
            acc += wv.x * q[c4 * 4 + 0] + wv.y * q[c4 * 4 + 1]
                 + wv.z * q[c4 * 4 + 2] + wv.w * q[c4 * 4 + 3];
        }
        g_resq[b * HH + h] = acc;
    }
}

// ---------------- kernel 2: mma.sync fused GEMM + tanh + Wo-reduce ----------
// CTA: 128 ctx rows (A fp16 resident in SMEM, swizzled), N=1024 in 16 tiles of
// 64, K=512. B (Wc fp16) streamed via cp.async double-buffer. 8 warps, each
// owns 16 M-rows. Register accumulators, fused FMA-tanh epilogue.
#define A_SZ   131072                 // 128 x 512 fp16
#define B_SZ   8192                   // 64 x 64 fp16
#define RQ_OFF (A_SZ + 2 * B_SZ)      // 147456
#define WO_OFF (RQ_OFF + 4096)
#define SM_REQ (WO_OFF + 4096 + 128)

__global__ __launch_bounds__(256, 1) void logits_mma_kernel(
    const float* __restrict__ ctx, const float* __restrict__ bc,
    const float* __restrict__ Wo, const float* __restrict__ bo) {
    extern __shared__ char smraw[];
    const uint32_t sb_raw = smem_u32(smraw);
    const uint32_t sb = (sb_raw + 127u) & ~127u;
    char* sm = smraw + (sb - sb_raw);

    const int t = threadIdx.x;
    const int lane = t & 31, warp = t >> 5;
    const int m_base = blockIdx.x * 128;
    const int b = blockIdx.x >> 4;            // 16 M-tiles per batch row

    float* rqs_s = (float*)(sm + RQ_OFF);
    float* wos_s = (float*)(sm + WO_OFF);
#pragma unroll
    for (int i = 0; i < 4; i++) {
        const int n = t + i * 256;
        rqs_s[n] = g_resq[b * HH + n] + bc[n];
        wos_s[n] = Wo[n];
    }

    // ---- fill A: ctx[m_base..+128][0..512] fp32 -> fp16 swizzled ----
    // chunk layout: A_off(row,c) = row*1024 + ((c ^ (row&7))<<4), c in [0,64)
#pragma unroll 8
    for (int i = 0; i < 32; i++) {
        const int idx = t + i * 256;
        const int row = idx >> 6, c = idx & 63;
        const float4* s = (const float4*)(ctx + (size_t)(m_base + row) * CC + c * 8);
        float4 v0 = s[0], v1 = s[1];
        __half2 h0 = __floats2half2_rn(v0.x, v0.y);
        __half2 h1 = __floats2half2_rn(v0.z, v0.w);
        __half2 h2 = __floats2half2_rn(v1.x, v1.y);
        __half2 h3 = __floats2half2_rn(v1.z, v1.w);
        uint4 u;
        u.x = *reinterpret_cast<uint32_t*>(&h0);
        u.y = *reinterpret_cast<uint32_t*>(&h1);
        u.z = *reinterpret_cast<uint32_t*>(&h2);
        u.w = *reinterpret_cast<uint32_t*>(&h3);
        *(uint4*)(sm + row * 1024 + (((c ^ (row & 7))) << 4)) = u;
    }

    const uint32_t sb_B = sb + A_SZ;

    // B fill: tile it = nt*8+kk -> 64 n-rows x 64 k fp16, swizzled
    auto fill_B = [&](int buf, int it) {
        const int ntv = it >> 3, kkv = it & 7;
#pragma unroll
        for (int i = 0; i < 2; i++) {
            const int idx = t + i * 256;
            const int row = idx >> 3, c = idx & 7;
            const __half* src = g_wc_h + (size_t)(ntv * 64 + row) * CC + kkv * 64 + c * 8;
            const uint32_t dst = sb_B + buf * B_SZ + row * 128 + (((c ^ (row & 7))) << 4);
            cp_async16(dst, src);
        }
        CP_COMMIT();
    };

    fill_B(0, 0);

    // ldmatrix lane addressing (precomputed parts)
    const uint32_t a_row_addr = sb + (warp * 16 + (lane & 15)) * 1024;
    const int a_hi = lane >> 4;               // +1 chunk for k+8 matrices
    const int asw = lane & 7;
    const int brow = (lane & 7) + ((lane & 16) >> 1);   // n row within 16-pair
    const int bkbit = (lane >> 3) & 1;
    const int bsw = lane & 7;

    float p0 = 0.f, p1 = 0.f;
    const float bo0 = bo[0];
    int it = 0;

    for (int nt = 0; nt < 16; nt++) {
        float acc[8][4];
#pragma unroll
        for (int i = 0; i < 8; i++)
#pragma unroll
            for (int j = 0; j < 4; j++) acc[i][j] = 0.f;

        for (int kk = 0; kk < 8; kk++, it++) {
            if (it + 1 < 128) { fill_B((it + 1) & 1, it + 1); CP_WAIT(1); }
            else              { CP_WAIT(0); }
            __syncthreads();
            const uint32_t bbuf = sb_B + (it & 1) * B_SZ;
#pragma unroll
            for (int ks = 0; ks < 4; ks++) {
                uint32_t a0, a1, a2, a3;
                const int c0 = kk * 8 + ks * 2 + a_hi;
                ldsm4(a0, a1, a2, a3, a_row_addr + ((uint32_t)(c0 ^ asw) << 4));
                const int chunk = ks * 2 + bkbit;
#pragma unroll
                for (int pq = 0; pq < 4; pq++) {
                    uint32_t b0, b1, b2, b3;
                    const uint32_t baddr = bbuf + (pq * 16 + brow) * 128
                                         + ((uint32_t)(chunk ^ bsw) << 4);
                    ldsm4(b0, b1, b2, b3, baddr);
                    mma16816(acc[2 * pq],     a0, a1, a2, a3, b0, b1);
                    mma16816(acc[2 * pq + 1], a0, a1, a2, a3, b2, b3);
                }
            }
            __syncthreads();
        }
        // ---- fused epilogue for this n-tile (registers only) ----
#pragma unroll
        for (int nb = 0; nb < 8; nb++) {
            const int ng = nt * 64 + nb * 8 + ((lane & 3) << 1);
            const float rq0 = rqs_s[ng],     w0 = wos_s[ng];
            const float rq1 = rqs_s[ng + 1], w1 = wos_s[ng + 1];
            p0 += w0 * tanh_fma(acc[nb][0] + rq0);
            p0 += w1 * tanh_fma(acc[nb][1] + rq1);
            p1 += w0 * tanh_fma(acc[nb][2] + rq0);
            p1 += w1 * tanh_fma(acc[nb][3] + rq1);
        }
    }

    // quad reduce (lanes sharing a row differ in lane%4)
    p0 += __shfl_xor_sync(0xffffffffu, p0, 1);
    p0 += __shfl_xor_sync(0xffffffffu, p0, 2);
    p1 += __shfl_xor_sync(0xffffffffu, p1, 1);
    p1 += __shfl_xor_sync(0xffffffffu, p1, 2);
    if ((lane & 3) == 0) {
        const int r = warp * 16 + (lane >> 2);
        g_logit[m_base + r]     = p0 + bo0;
        g_logit[m_base + r + 8] = p1 + bo0;
    }
}

// ---------------- kernel 3: masked exp + normalize over L ----------------
__global__ void softmax_kernel(const float* __restrict__ mask,
                               float* __restrict__ w_out, int write_w) {
    __shared__ float sred[256];
    const int b = blockIdx.x, t = threadIdx.x;
    float e[8];
    float s = 0.f;
#pragma unroll
    for (int i = 0; i < 8; i++) {
        const int l = t + i * 256;
        const float ev = mask[b * LL + l] * expf(g_logit[b * LL + l]);
        e[i] = ev;
        s += ev;
    }
    sred[t] = s;
    __syncthreads();
#pragma unroll
    for (int off = 128; off > 0; off >>= 1) {
        if (t < off) sred[t] += sred[t + off];
        __syncthreads();
    }
    const float inv = 1.f / (sred[0] + 1e-5f);
#pragma unroll
    for (int i = 0; i < 8; i++) {
        const int l = t + i * 256;
        const float wv = e[i] * inv;
        g_weights[b * LL + l] = wv;
        if (write_w) w_out[b * LL + l] = wv;
    }
}

// ---------------- kernel 4: weighted sum over L (32-way split) ----------------
__global__ void wsum_kernel(const float* __restrict__ ctx) {
    const int b = blockIdx.x, ls = blockIdx.y, t = threadIdx.x;
    __shared__ float ws[64];
    if (t < 64) ws[t] = g_weights[b * LL + ls * 64 + t];
    __syncthreads();
    float a0 = 0.f, a1 = 0.f;
    const size_t base_l = (size_t)b * LL + ls * 64;
#pragma unroll 4
    for (int li = 0; li < 64; li++) {
        const float w = ws[li];
        const float* row = ctx + (base_l + li) * CC;
        a0 += w * row[t];
        a1 += w * row[256 + t];
    }
    g_part[(size_t)(b * 32 + ls) * CC + t] = a0;
    g_part[(size_t)(b * 32 + ls) * CC + 256 + t] = a1;
}

__global__ void reduce_kernel(float* __restrict__ out_vec) {
    const int idx = blockIdx.x * 256 + threadIdx.x;  // 0..16383
    const int b = idx >> 9, c = idx & 511;
    float s = 0.f;
#pragma unroll
    for (int ls = 0; ls < 32; ls++) s += g_part[(size_t)(b * 32 + ls) * CC + c];
    out_vec[b * CC + c] = s;
}

// ---------------- launch ----------------
extern "C" void kernel_launch(void* const* d_in, const int* in_sizes, int n_in,
                              void* d_out, int out_size) {
    const float* query   = (const float*)d_in[0];
    const float* context = (const float*)d_in[1];
    const float* mask    = (const float*)d_in[2];
    const float* Wq      = (const float*)d_in[3];
    const float* Wc      = (const float*)d_in[4];
    const float* bc      = (const float*)d_in[5];
    const float* Wo      = (const float*)d_in[6];
    const float* bo      = (const float*)d_in[7];

    float* out = (float*)d_out;
    float* out_vec = nullptr;
    float* out_w = nullptr;
    if (out_size >= BB * CC + BB * LL) {
        out_vec = out;
        out_w = out + BB * CC;
    } else if (out_size == BB * LL) {
        out_w = out;
    } else {
        out_vec = out;
    }

    cudaFuncSetAttribute(logits_mma_kernel,
                         cudaFuncAttributeMaxDynamicSharedMemorySize, SM_REQ);

    wcprep_kernel<<<512, 256>>>(Wc);
    resq_kernel<<<BB, 256>>>(query, Wq);
    logits_mma_kernel<<<512, 256, SM_REQ>>>(context, bc, Wo, bo);
    softmax_kernel<<<BB, 256>>>(mask, out_w, out_w != nullptr ? 1 : 0);
    wsum_kernel<<<dim3(BB, 32), 256>>>(context);
    if (out_vec) reduce_kernel<<<(BB * CC) / 256, 256>>>(out_vec);
}

// round 5
// speedup vs baseline: 4.9479x; 1.1805x over previous
#include <cuda_runtime.h>
#include <cuda_fp16.h>
#include <cstdint>

#define BB 32
#define LL 2048
#define CC 512
#define QQ 512
#define HH 1024

// ---------------- scratch (no allocations allowed) ----------------
__device__ float g_resq[BB * HH];          // 128 KB
__device__ float g_logit[BB * LL];         // 256 KB
__device__ float g_weights[BB * LL];       // 256 KB
__device__ float g_part[BB * 32 * CC];     // 2 MB
__device__ __half g_wc_h[HH * CC];         // 1 MB  (Wc in fp16, [h][k])

// ---------------- helpers ----------------
__device__ __forceinline__ uint32_t smem_u32(const void* p) {
    uint32_t a;
    asm("{ .reg .u64 t; cvta.to.shared.u64 t, %1; cvt.u32.u64 %0, t; }"
        : "=r"(a) : "l"(p));
    return a;
}

__device__ __forceinline__ void ldsm4(uint32_t& r0, uint32_t& r1,
                                      uint32_t& r2, uint32_t& r3, uint32_t addr) {
    asm volatile("ldmatrix.sync.aligned.m8n8.x4.shared.b16 {%0,%1,%2,%3}, [%4];"
                 : "=r"(r0), "=r"(r1), "=r"(r2), "=r"(r3) : "r"(addr));
}

__device__ __forceinline__ void mma16816(float* c,
                                         uint32_t a0, uint32_t a1, uint32_t a2, uint32_t a3,
                                         uint32_t b0, uint32_t b1) {
    asm volatile(
        "mma.sync.aligned.m16n8k16.row.col.f32.f16.f16.f32 "
        "{%0,%1,%2,%3}, {%4,%5,%6,%7}, {%8,%9}, {%0,%1,%2,%3};"
        : "+f"(c[0]), "+f"(c[1]), "+f"(c[2]), "+f"(c[3])
        : "r"(a0), "r"(a1), "r"(a2), "r"(a3), "r"(b0), "r"(b1));
}

__device__ __forceinline__ void cp_async16(uint32_t dst, const void* src) {
    asm volatile("cp.async.cg.shared.global [%0], [%1], 16;" :: "r"(dst), "l"(src));
}
#define CP_COMMIT() asm volatile("cp.async.commit_group;" ::: "memory")
#define CP_WAIT0()  asm volatile("cp.async.wait_group 0;" ::: "memory")

// MUFU-pipe tanh: 2 MUFU + ~4 FMA. Overlaps with tensor/FMA pipes.
__device__ __forceinline__ float tanh_mufu(float x) {
    float t = __expf(2.0f * x);                  // ex2.approx path
    return 1.0f - __fdividef(2.0f, t + 1.0f);    // rcp.approx path
}

// ---------------- kernel 0: Wc -> fp16 ----------------
__global__ void wcprep_kernel(const float* __restrict__ Wc) {
    const int i = blockIdx.x * 256 + threadIdx.x;    // 131072 float4s
    float4 v = reinterpret_cast<const float4*>(Wc)[i];
    __half2 h0 = __floats2half2_rn(v.x, v.y);
    __half2 h1 = __floats2half2_rn(v.z, v.w);
    uint2 u;
    u.x = *reinterpret_cast<uint32_t*>(&h0);
    u.y = *reinterpret_cast<uint32_t*>(&h1);
    reinterpret_cast<uint2*>(g_wc_h)[i] = u;
}

// ---------------- kernel 1: res_q = query @ Wq^T ----------------
__global__ void resq_kernel(const float* __restrict__ query,
                            const float* __restrict__ Wq) {
    __shared__ float q[QQ];
    const int b = blockIdx.x, t = threadIdx.x;
    for (int i = t; i < QQ; i += 256) q[i] = query[b * QQ + i];
    __syncthreads();
#pragma unroll
    for (int j = 0; j < 4; j++) {
        const int h = t + j * 256;
        const float4* w = (const float4*)(Wq + (size_t)h * QQ);
        float acc = 0.f;
#pragma unroll 8
        for (int c4 = 0; c4 < QQ / 4; c4++) {
            float4 wv = w[c4];
            acc += wv.x * q[c4 * 4 + 0] + wv.y * q[c4 * 4 + 1]
                 + wv.z * q[c4 * 4 + 2] + wv.w * q[c4 * 4 + 3];
        }
        g_resq[b * HH + h] = acc;
    }
}

// ---------------- kernel 2: mma.sync fused GEMM + tanh + Wo-reduce ----------
// CTA: M=128 ctx rows (A fp16 resident, swizzled). N=1024 in 8 tiles of 128.
// K=512 in 8 chunks of 64 -> 64 iterations, ONE barrier each.
// Warps 4Mx2N: warp tile 32M x 64N. B (128n x 64k = 16KB) cp.async dbl-buffer.
// Logit = sum over BOTH ng warps: ng=1 stages partials in SMEM, ng=0 combines.
#define A_SZ   131072                 // 128 x 512 fp16
#define B_SZ   16384                  // 128 x 64 fp16
#define RQ_OFF (A_SZ + 2 * B_SZ)      // 163840
#define WO_OFF (RQ_OFF + 4096)
#define RED_OFF (WO_OFF + 4096)
#define SM_REQ (RED_OFF + 512 + 128)

__global__ __launch_bounds__(256, 1) void logits_mma_kernel(
    const float* __restrict__ ctx, const float* __restrict__ bc,
    const float* __restrict__ Wo, const float* __restrict__ bo) {
    extern __shared__ char smraw[];
    const uint32_t sb_raw = smem_u32(smraw);
    const uint32_t sb = (sb_raw + 127u) & ~127u;
    char* sm = smraw + (sb - sb_raw);

    const int t = threadIdx.x;
    const int lane = t & 31, warp = t >> 5;
    const int mg = warp >> 1;                 // 0..3: M group (32 rows)
    const int ng = warp & 1;                  // 0..1: N group (64 cols)
    const int m_base = blockIdx.x * 128;
    const int b = blockIdx.x >> 4;            // 16 M-tiles per batch row

    float* rqs_s = (float*)(sm + RQ_OFF);
    float* wos_s = (float*)(sm + WO_OFF);
    float* red_s = (float*)(sm + RED_OFF);
#pragma unroll
    for (int i = 0; i < 4; i++) {
        const int n = t + i * 256;
        rqs_s[n] = g_resq[b * HH + n] + bc[n];
        wos_s[n] = Wo[n];
    }

    // ---- fill A: ctx[m_base..+128][0..512] fp32 -> fp16 swizzled ----
    // A_off(row,c) = row*1024 + ((c ^ (row&7))<<4), c = 16B chunk in [0,64)
#pragma unroll 8
    for (int i = 0; i < 32; i++) {
        const int idx = t + i * 256;
        const int row = idx >> 6, c = idx & 63;
        const float4* s = (const float4*)(ctx + (size_t)(m_base + row) * CC + c * 8);
        float4 v0 = s[0], v1 = s[1];
        __half2 h0 = __floats2half2_rn(v0.x, v0.y);
        __half2 h1 = __floats2half2_rn(v0.z, v0.w);
        __half2 h2 = __floats2half2_rn(v1.x, v1.y);
        __half2 h3 = __floats2half2_rn(v1.z, v1.w);
        uint4 u;
        u.x = *reinterpret_cast<uint32_t*>(&h0);
        u.y = *reinterpret_cast<uint32_t*>(&h1);
        u.z = *reinterpret_cast<uint32_t*>(&h2);
        u.w = *reinterpret_cast<uint32_t*>(&h3);
        *(uint4*)(sm + row * 1024 + (((c ^ (row & 7))) << 4)) = u;
    }

    const uint32_t sb_B = sb + A_SZ;

    // B fill: it = nt*8+kk -> 128 n-rows x 64 k fp16, swizzled; 4 cp.async/thread
    auto fill_B = [&](int buf, int it) {
        const int ntv = it >> 3, kkv = it & 7;
#pragma unroll
        for (int i = 0; i < 4; i++) {
            const int idx = t + i * 256;
            const int row = idx >> 3, c = idx & 7;
            const __half* src = g_wc_h + (size_t)(ntv * 128 + row) * CC + kkv * 64 + c * 8;
            const uint32_t dst = sb_B + buf * B_SZ + row * 128 + (((c ^ (row & 7))) << 4);
            cp_async16(dst, src);
        }
        CP_COMMIT();
    };

    fill_B(0, 0);

    // ldmatrix lane addressing
    const uint32_t a_row_addr = sb + (mg * 32 + (lane & 15)) * 1024;
    const int a_hi = lane >> 4;                       // +1 chunk for k+8
    const int asw = lane & 7;
    const int brow = (lane & 7) + ((lane & 16) >> 1); // n-row within 16-pair
    const int bkbit = (lane >> 3) & 1;
    const int bsw = lane & 7;

    float p[4] = {0.f, 0.f, 0.f, 0.f};
    const float bo0 = bo[0];

    float acc[2][8][4];
    for (int it = 0; it < 64; it++) {
        const int nt = it >> 3, kk = it & 7;
        if (kk == 0) {
#pragma unroll
            for (int mt = 0; mt < 2; mt++)
#pragma unroll
                for (int nb = 0; nb < 8; nb++)
#pragma unroll
                    for (int j = 0; j < 4; j++) acc[mt][nb][j] = 0.f;
        }

        CP_WAIT0();
        __syncthreads();                 // publishes B(it); retires B(it-1) consumers
        if (it + 1 < 64) fill_B((it + 1) & 1, it + 1);

        const uint32_t bbase = sb_B + (uint32_t)(it & 1) * B_SZ + (uint32_t)ng * 64 * 128;
#pragma unroll
        for (int ks = 0; ks < 4; ks++) {
            uint32_t a[2][4];
            const int c0 = kk * 8 + ks * 2 + a_hi;
            const uint32_t aoff = (uint32_t)(c0 ^ asw) << 4;
            ldsm4(a[0][0], a[0][1], a[0][2], a[0][3], a_row_addr + aoff);
            ldsm4(a[1][0], a[1][1], a[1][2], a[1][3], a_row_addr + 16384 + aoff);
            const int chunk = ks * 2 + bkbit;
            uint32_t bf[4][4];
#pragma unroll
            for (int pq = 0; pq < 4; pq++) {
                const uint32_t baddr = bbase + (uint32_t)(pq * 16 + brow) * 128
                                     + ((uint32_t)(chunk ^ bsw) << 4);
                ldsm4(bf[pq][0], bf[pq][1], bf[pq][2], bf[pq][3], baddr);
            }
#pragma unroll
            for (int mt = 0; mt < 2; mt++)
#pragma unroll
                for (int pq = 0; pq < 4; pq++) {
                    mma16816(acc[mt][2 * pq],     a[mt][0], a[mt][1], a[mt][2], a[mt][3],
                             bf[pq][0], bf[pq][1]);
                    mma16816(acc[mt][2 * pq + 1], a[mt][0], a[mt][1], a[mt][2], a[mt][3],
                             bf[pq][2], bf[pq][3]);
                }
        }

        if (kk == 7) {
            // ---- fused epilogue for n-tile nt (registers + MUFU only) ----
#pragma unroll
            for (int mt = 0; mt < 2; mt++)
#pragma unroll
                for (int nb = 0; nb < 8; nb++) {
                    const int ngl = nt * 128 + ng * 64 + nb * 8 + ((lane & 3) << 1);
                    const float rq0 = rqs_s[ngl],     w0 = wos_s[ngl];
                    const float rq1 = rqs_s[ngl + 1], w1 = wos_s[ngl + 1];
                    p[2 * mt]     += w0 * tanh_mufu(acc[mt][nb][0] + rq0);
                    p[2 * mt]     += w1 * tanh_mufu(acc[mt][nb][1] + rq1);
                    p[2 * mt + 1] += w0 * tanh_mufu(acc[mt][nb][2] + rq0);
                    p[2 * mt + 1] += w1 * tanh_mufu(acc[mt][nb][3] + rq1);
                }
        }
    }

    // quad reduce (accumulating lanes differ in lane%4)
#pragma unroll
    for (int j = 0; j < 4; j++) {
        p[j] += __shfl_xor_sync(0xffffffffu, p[j], 1);
        p[j] += __shfl_xor_sync(0xffffffffu, p[j], 2);
    }
    // combine the two ng halves: ng=1 stages, ng=0 adds and writes
    if (ng == 1 && (lane & 3) == 0) {
        float* dst = red_s + (mg * 8 + (lane >> 2)) * 4;
        dst[0] = p[0]; dst[1] = p[1]; dst[2] = p[2]; dst[3] = p[3];
    }
    __syncthreads();
    if (ng == 0 && (lane & 3) == 0) {
        const float* src = red_s + (mg * 8 + (lane >> 2)) * 4;
        const int r0 = mg * 32 + (lane >> 2);
        g_logit[m_base + r0]      = p[0] + src[0] + bo0;
        g_logit[m_base + r0 + 8]  = p[1] + src[1] + bo0;
        g_logit[m_base + r0 + 16] = p[2] + src[2] + bo0;
        g_logit[m_base + r0 + 24] = p[3] + src[3] + bo0;
    }
}

// ---------------- kernel 3: masked exp + normalize over L ----------------
__global__ void softmax_kernel(const float* __restrict__ mask,
                               float* __restrict__ w_out, int write_w) {
    __shared__ float sred[256];
    const int b = blockIdx.x, t = threadIdx.x;
    float e[8];
    float s = 0.f;
#pragma unroll
    for (int i = 0; i < 8; i++) {
        const int l = t + i * 256;
        const float ev = mask[b * LL + l] * expf(g_logit[b * LL + l]);
        e[i] = ev;
        s += ev;
    }
    sred[t] = s;
    __syncthreads();
#pragma unroll
    for (int off = 128; off > 0; off >>= 1) {
        if (t < off) sred[t] += sred[t + off];
        __syncthreads();
    }
    const float inv = 1.f / (sred[0] + 1e-5f);
#pragma unroll
    for (int i = 0; i < 8; i++) {
        const int l = t + i * 256;
        const float wv = e[i] * inv;
        g_weights[b * LL + l] = wv;
        if (write_w) w_out[b * LL + l] = wv;
    }
}

// ---------------- kernel 4: weighted sum over L (32-way split, float2) -----
__global__ void wsum_kernel(const float* __restrict__ ctx) {
    const int b = blockIdx.x, ls = blockIdx.y, t = threadIdx.x;
    __shared__ float ws[64];
    if (t < 64) ws[t] = g_weights[b * LL + ls * 64 + t];
    __syncthreads();
    float ax = 0.f, ay = 0.f;
    const float2* base = (const float2*)(ctx + ((size_t)b * LL + ls * 64) * CC) + t;
#pragma unroll 8
    for (int li = 0; li < 64; li++) {
        const float2 v = base[li * 256];
        const float w = ws[li];
        ax += w * v.x;
        ay += w * v.y;
    }
    float* dst = g_part + (size_t)(b * 32 + ls) * CC + t * 2;
    dst[0] = ax;
    dst[1] = ay;
}

__global__ void reduce_kernel(float* __restrict__ out_vec) {
    const int idx = blockIdx.x * 256 + threadIdx.x;  // 0..16383
    const int b = idx >> 9, c = idx & 511;
    float s = 0.f;
#pragma unroll
    for (int ls = 0; ls < 32; ls++) s += g_part[(size_t)(b * 32 + ls) * CC + c];
    out_vec[b * CC + c] = s;
}

// ---------------- launch ----------------
extern "C" void kernel_launch(void* const* d_in, const int* in_sizes, int n_in,
                              void* d_out, int out_size) {
    const float* query   = (const float*)d_in[0];
    const float* context = (const float*)d_in[1];
    const float* mask    = (const float*)d_in[2];
    const float* Wq      = (const float*)d_in[3];
    const float* Wc      = (const float*)d_in[4];
    const float* bc      = (const float*)d_in[5];
    const float* Wo      = (const float*)d_in[6];
    const float* bo      = (const float*)d_in[7];

    float* out = (float*)d_out;
    float* out_vec = nullptr;
    float* out_w = nullptr;
    if (out_size >= BB * CC + BB * LL) {
        out_vec = out;
        out_w = out + BB * CC;
    } else if (out_size == BB * LL) {
        out_w = out;
    } else {
        out_vec = out;
    }

    cudaFuncSetAttribute(logits_mma_kernel,
                         cudaFuncAttributeMaxDynamicSharedMemorySize, SM_REQ);

    wcprep_kernel<<<512, 256>>>(Wc);
    resq_kernel<<<BB, 256>>>(query, Wq);
    logits_mma_kernel<<<512, 256, SM_REQ>>>(context, bc, Wo, bo);
    softmax_kernel<<<BB, 256>>>(mask, out_w, out_w != nullptr ? 1 : 0);
    wsum_kernel<<<dim3(BB, 32), 256>>>(context);
    if (out_vec) reduce_kernel<<<(BB * CC) / 256, 256>>>(out_vec);
}

// round 6
// speedup vs baseline: 5.5669x; 1.1251x over previous
#include <cuda_runtime.h>
#include <cuda_fp16.h>
#include <cstdint>

#define BB 32
#define LL 2048
#define CC 512
#define QQ 512
#define HH 1024

// ---------------- scratch (no allocations allowed) ----------------
__device__ float g_resq[BB * HH];          // 128 KB
__device__ float g_logit[BB * LL];         // 256 KB
__device__ float g_weights[BB * LL];       // 256 KB
__device__ float g_part[BB * 32 * CC];     // 2 MB
__device__ __half g_wc_h[HH * CC];         // 1 MB  (Wc in fp16, [h][k])

// ---------------- helpers ----------------
__device__ __forceinline__ uint32_t smem_u32(const void* p) {
    uint32_t a;
    asm("{ .reg .u64 t; cvta.to.shared.u64 t, %1; cvt.u32.u64 %0, t; }"
        : "=r"(a) : "l"(p));
    return a;
}

__device__ __forceinline__ void ldsm4(uint32_t& r0, uint32_t& r1,
                                      uint32_t& r2, uint32_t& r3, uint32_t addr) {
    asm volatile("ldmatrix.sync.aligned.m8n8.x4.shared.b16 {%0,%1,%2,%3}, [%4];"
                 : "=r"(r0), "=r"(r1), "=r"(r2), "=r"(r3) : "r"(addr));
}

__device__ __forceinline__ void mma16816(float* c,
                                         uint32_t a0, uint32_t a1, uint32_t a2, uint32_t a3,
                                         uint32_t b0, uint32_t b1) {
    asm volatile(
        "mma.sync.aligned.m16n8k16.row.col.f32.f16.f16.f32 "
        "{%0,%1,%2,%3}, {%4,%5,%6,%7}, {%8,%9}, {%0,%1,%2,%3};"
        : "+f"(c[0]), "+f"(c[1]), "+f"(c[2]), "+f"(c[3])
        : "r"(a0), "r"(a1), "r"(a2), "r"(a3), "r"(b0), "r"(b1));
}

__device__ __forceinline__ void cp_async16(uint32_t dst, const void* src) {
    asm volatile("cp.async.cg.shared.global [%0], [%1], 16;" :: "r"(dst), "l"(src));
}
#define CP_COMMIT() asm volatile("cp.async.commit_group;" ::: "memory")
#define CP_WAIT0()  asm volatile("cp.async.wait_group 0;" ::: "memory")

// MUFU-pipe tanh: 2 MUFU + ~4 FMA. Overlaps with tensor/FMA pipes.
__device__ __forceinline__ float tanh_mufu(float x) {
    float t = __expf(2.0f * x);                  // ex2.approx path
    return 1.0f - __fdividef(2.0f, t + 1.0f);    // rcp.approx path
}

// ---------------- kernel 0: Wc -> fp16 ----------------
__global__ void wcprep_kernel(const float* __restrict__ Wc) {
    const int i = blockIdx.x * 256 + threadIdx.x;    // 131072 float4s
    float4 v = reinterpret_cast<const float4*>(Wc)[i];
    __half2 h0 = __floats2half2_rn(v.x, v.y);
    __half2 h1 = __floats2half2_rn(v.z, v.w);
    uint2 u;
    u.x = *reinterpret_cast<uint32_t*>(&h0);
    u.y = *reinterpret_cast<uint32_t*>(&h1);
    reinterpret_cast<uint2*>(g_wc_h)[i] = u;
}

// ---------------- kernel 1: res_q = query @ Wq^T ----------------
__global__ void resq_kernel(const float* __restrict__ query,
                            const float* __restrict__ Wq) {
    __shared__ float q[QQ];
    const int b = blockIdx.x, t = threadIdx.x;
    for (int i = t; i < QQ; i += 256) q[i] = query[b * QQ + i];
    __syncthreads();
#pragma unroll
    for (int j = 0; j < 4; j++) {
        const int h = t + j * 256;
        const float4* w = (const float4*)(Wq + (size_t)h * QQ);
        float acc = 0.f;
#pragma unroll 8
        for (int c4 = 0; c4 < QQ / 4; c4++) {
            float4 wv = w[c4];
            acc += wv.x * q[c4 * 4 + 0] + wv.y * q[c4 * 4 + 1]
                 + wv.z * q[c4 * 4 + 2] + wv.w * q[c4 * 4 + 3];
        }
        g_resq[b * HH + h] = acc;
    }
}

// ---------------- kernel 2: mma.sync fused GEMM + tanh + Wo-reduce ----------
// OCCUPANCY 2: CTA = M=64 ctx rows (A fp16 resident, 64KB swizzled).
// N=1024 in 8 tiles of 128; K=512 in 8 chunks of 64 -> 64 iterations.
// Warps 2Mx4N: warp tile 32M x 32N. B (128n x 64k = 16KB) cp.async dbl-buffer.
// ~105KB SMEM/CTA -> 2 CTAs/SM; 4 warps/SMSP hide MMA/LDSM/cp.async latency.
#define A_SZ    65536                 // 64 x 512 fp16
#define B_SZ    16384                 // 128 x 64 fp16
#define RQ_OFF  (A_SZ + 2 * B_SZ)     // 98304
#define WO_OFF  (RQ_OFF + 4096)
#define RED_OFF (WO_OFF + 4096)
#define SM_REQ  (RED_OFF + 768 + 128)

__global__ __launch_bounds__(256, 2) void logits_mma_kernel(
    const float* __restrict__ ctx, const float* __restrict__ bc,
    const float* __restrict__ Wo, const float* __restrict__ bo) {
    extern __shared__ char smraw[];
    const uint32_t sb_raw = smem_u32(smraw);
    const uint32_t sb = (sb_raw + 127u) & ~127u;
    char* sm = smraw + (sb - sb_raw);

    const int t = threadIdx.x;
    const int lane = t & 31, warp = t >> 5;
    const int mg = warp >> 2;                 // 0..1: M group (32 rows)
    const int ng = warp & 3;                  // 0..3: N group (32 cols)
    const int m_base = blockIdx.x * 64;
    const int b = blockIdx.x >> 5;            // 32 M-tiles per batch row

    float* rqs_s = (float*)(sm + RQ_OFF);
    float* wos_s = (float*)(sm + WO_OFF);
    float* red_s = (float*)(sm + RED_OFF);
#pragma unroll
    for (int i = 0; i < 4; i++) {
        const int n = t + i * 256;
        rqs_s[n] = g_resq[b * HH + n] + bc[n];
        wos_s[n] = Wo[n];
    }

    // ---- fill A: ctx[m_base..+64][0..512] fp32 -> fp16 swizzled ----
    // A_off(row,c) = row*1024 + ((c ^ (row&7))<<4), c = 16B chunk in [0,64)
#pragma unroll 4
    for (int i = 0; i < 16; i++) {
        const int idx = t + i * 256;
        const int row = idx >> 6, c = idx & 63;
        const float4* s = (const float4*)(ctx + (size_t)(m_base + row) * CC + c * 8);
        float4 v0 = s[0], v1 = s[1];
        __half2 h0 = __floats2half2_rn(v0.x, v0.y);
        __half2 h1 = __floats2half2_rn(v0.z, v0.w);
        __half2 h2 = __floats2half2_rn(v1.x, v1.y);
        __half2 h3 = __floats2half2_rn(v1.z, v1.w);
        uint4 u;
        u.x = *reinterpret_cast<uint32_t*>(&h0);
        u.y = *reinterpret_cast<uint32_t*>(&h1);
        u.z = *reinterpret_cast<uint32_t*>(&h2);
        u.w = *reinterpret_cast<uint32_t*>(&h3);
        *(uint4*)(sm + row * 1024 + (((c ^ (row & 7))) << 4)) = u;
    }

    const uint32_t sb_B = sb + A_SZ;

    // B fill: it = nt*8+kk -> 128 n-rows x 64 k fp16, swizzled; 4 cp.async/thread
    auto fill_B = [&](int buf, int it) {
        const int ntv = it >> 3, kkv = it & 7;
#pragma unroll
        for (int i = 0; i < 4; i++) {
            const int idx = t + i * 256;
            const int row = idx >> 3, c = idx & 7;
            const __half* src = g_wc_h + (size_t)(ntv * 128 + row) * CC + kkv * 64 + c * 8;
            const uint32_t dst = sb_B + buf * B_SZ + row * 128 + (((c ^ (row & 7))) << 4);
            cp_async16(dst, src);
        }
        CP_COMMIT();
    };

    fill_B(0, 0);

    // ldmatrix lane addressing
    const uint32_t a_row_addr = sb + (mg * 32 + (lane & 15)) * 1024;
    const int a_hi = lane >> 4;                       // +1 chunk for k+8
    const int asw = lane & 7;
    const int brow = (lane & 7) + ((lane & 16) >> 1); // n-row within 16-pair
    const int bkbit = (lane >> 3) & 1;
    const int bsw = lane & 7;

    float p[4] = {0.f, 0.f, 0.f, 0.f};
    const float bo0 = bo[0];

    float acc[2][4][4];
    for (int it = 0; it < 64; it++) {
        const int nt = it >> 3, kk = it & 7;
        if (kk == 0) {
#pragma unroll
            for (int mt = 0; mt < 2; mt++)
#pragma unroll
                for (int nb = 0; nb < 4; nb++)
#pragma unroll
                    for (int j = 0; j < 4; j++) acc[mt][nb][j] = 0.f;
        }

        CP_WAIT0();
        __syncthreads();                 // publishes B(it); retires B(it-1) consumers
        if (it + 1 < 64) fill_B((it + 1) & 1, it + 1);

        const uint32_t bbase = sb_B + (uint32_t)(it & 1) * B_SZ + (uint32_t)ng * 32 * 128;
#pragma unroll
        for (int ks = 0; ks < 4; ks++) {
            uint32_t a[2][4];
            const int c0 = kk * 8 + ks * 2 + a_hi;
            const uint32_t aoff = (uint32_t)(c0 ^ asw) << 4;
            ldsm4(a[0][0], a[0][1], a[0][2], a[0][3], a_row_addr + aoff);
            ldsm4(a[1][0], a[1][1], a[1][2], a[1][3], a_row_addr + 16384 + aoff);
            const int chunk = ks * 2 + bkbit;
            uint32_t bf[2][4];
#pragma unroll
            for (int pq = 0; pq < 2; pq++) {
                const uint32_t baddr = bbase + (uint32_t)(pq * 16 + brow) * 128
                                     + ((uint32_t)(chunk ^ bsw) << 4);
                ldsm4(bf[pq][0], bf[pq][1], bf[pq][2], bf[pq][3], baddr);
            }
#pragma unroll
            for (int mt = 0; mt < 2; mt++)
#pragma unroll
                for (int pq = 0; pq < 2; pq++) {
                    mma16816(acc[mt][2 * pq],     a[mt][0], a[mt][1], a[mt][2], a[mt][3],
                             bf[pq][0], bf[pq][1]);
                    mma16816(acc[mt][2 * pq + 1], a[mt][0], a[mt][1], a[mt][2], a[mt][3],
                             bf[pq][2], bf[pq][3]);
                }
        }

        if (kk == 7) {
            // ---- fused epilogue for n-tile nt (registers + MUFU only) ----
#pragma unroll
            for (int mt = 0; mt < 2; mt++)
#pragma unroll
                for (int nb = 0; nb < 4; nb++) {
                    const int ngl = nt * 128 + ng * 32 + nb * 8 + ((lane & 3) << 1);
                    const float rq0 = rqs_s[ngl],     w0 = wos_s[ngl];
                    const float rq1 = rqs_s[ngl + 1], w1 = wos_s[ngl + 1];
                    p[2 * mt]     += w0 * tanh_mufu(acc[mt][nb][0] + rq0);
                    p[2 * mt]     += w1 * tanh_mufu(acc[mt][nb][1] + rq1);
                    p[2 * mt + 1] += w0 * tanh_mufu(acc[mt][nb][2] + rq0);
                    p[2 * mt + 1] += w1 * tanh_mufu(acc[mt][nb][3] + rq1);
                }
        }
    }

    // quad reduce (accumulating lanes differ in lane%4)
#pragma unroll
    for (int j = 0; j < 4; j++) {
        p[j] += __shfl_xor_sync(0xffffffffu, p[j], 1);
        p[j] += __shfl_xor_sync(0xffffffffu, p[j], 2);
    }
    // combine the four ng quarters: ng=1..3 stage, ng=0 adds and writes.
    // p[j] holds row (mg*32 + (lane>>2) + 8*j), j=0..3.
    if (ng > 0 && (lane & 3) == 0) {
        float* dst = red_s + (ng - 1) * 64 + mg * 32 + (lane >> 2);
        dst[0]  = p[0];
        dst[8]  = p[1];
        dst[16] = p[2];
        dst[24] = p[3];
    }
    __syncthreads();
    if (ng == 0 && (lane & 3) == 0) {
        const int r = mg * 32 + (lane >> 2);
#pragma unroll
        for (int j = 0; j < 4; j++) {
            const int row = r + 8 * j;
            g_logit[m_base + row] = p[j] + red_s[row] + red_s[64 + row]
                                  + red_s[128 + row] + bo0;
        }
    }
}

// ---------------- kernel 3: masked exp + normalize over L ----------------
__global__ void softmax_kernel(const float* __restrict__ mask,
                               float* __restrict__ w_out, int write_w) {
    __shared__ float sred[256];
    const int b = blockIdx.x, t = threadIdx.x;
    float e[8];
    float s = 0.f;
#pragma unroll
    for (int i = 0; i < 8; i++) {
        const int l = t + i * 256;
        const float ev = mask[b * LL + l] * expf(g_logit[b * LL + l]);
        e[i] = ev;
        s += ev;
    }
    sred[t] = s;
    __syncthreads();
#pragma unroll
    for (int off = 128; off > 0; off >>= 1) {
        if (t < off) sred[t] += sred[t + off];
        __syncthreads();
    }
    const float inv = 1.f / (sred[0] + 1e-5f);
#pragma unroll
    for (int i = 0; i < 8; i++) {
        const int l = t + i * 256;
        const float wv = e[i] * inv;
        g_weights[b * LL + l] = wv;
        if (write_w) w_out[b * LL + l] = wv;
    }
}

// ---------------- kernel 4: weighted sum over L (32-way split, float2) -----
__global__ void wsum_kernel(const float* __restrict__ ctx) {
    const int b = blockIdx.x, ls = blockIdx.y, t = threadIdx.x;
    __shared__ float ws[64];
    if (t < 64) ws[t] = g_weights[b * LL + ls * 64 + t];
    __syncthreads();
    float ax = 0.f, ay = 0.f;
    const float2* base = (const float2*)(ctx + ((size_t)b * LL + ls * 64) * CC) + t;
#pragma unroll 8
    for (int li = 0; li < 64; li++) {
        const float2 v = base[li * 256];
        const float w = ws[li];
        ax += w * v.x;
        ay += w * v.y;
    }
    float* dst = g_part + (size_t)(b * 32 + ls) * CC + t * 2;
    dst[0] = ax;
    dst[1] = ay;
}

__global__ void reduce_kernel(float* __restrict__ out_vec) {
    const int idx = blockIdx.x * 256 + threadIdx.x;  // 0..16383
    const int b = idx >> 9, c = idx & 511;
    float s = 0.f;
#pragma unroll
    for (int ls = 0; ls < 32; ls++) s += g_part[(size_t)(b * 32 + ls) * CC + c];
    out_vec[b * CC + c] = s;
}

// ---------------- launch ----------------
extern "C" void kernel_launch(void* const* d_in, const int* in_sizes, int n_in,
                              void* d_out, int out_size) {
    const float* query   = (const float*)d_in[0];
    const float* context = (const float*)d_in[1];
    const float* mask    = (const float*)d_in[2];
    const float* Wq      = (const float*)d_in[3];
    const float* Wc      = (const float*)d_in[4];
    const float* bc      = (const float*)d_in[5];
    const float* Wo      = (const float*)d_in[6];
    const float* bo      = (const float*)d_in[7];

    float* out = (float*)d_out;
    float* out_vec = nullptr;
    float* out_w = nullptr;
    if (out_size >= BB * CC + BB * LL) {
        out_vec = out;
        out_w = out + BB * CC;
    } else if (out_size == BB * LL) {
        out_w = out;
    } else {
        out_vec = out;
    }

    cudaFuncSetAttribute(logits_mma_kernel,
                         cudaFuncAttributeMaxDynamicSharedMemorySize, SM_REQ);

    wcprep_kernel<<<512, 256>>>(Wc);
    resq_kernel<<<BB, 256>>>(query, Wq);
    logits_mma_kernel<<<(BB * LL) / 64, 256, SM_REQ>>>(context, bc, Wo, bo);
    softmax_kernel<<<BB, 256>>>(mask, out_w, out_w != nullptr ? 1 : 0);
    wsum_kernel<<<dim3(BB, 32), 256>>>(context);
    if (out_vec) reduce_kernel<<<(BB * CC) / 256, 256>>>(out_vec);
}

// round 7
// speedup vs baseline: 7.9173x; 1.4222x over previous
#include <cuda_runtime.h>
#include <cuda_fp16.h>
#include <cstdint>

#define BB 32
#define LL 2048
#define CC 512
#define QQ 512
#define HH 1024

// ---------------- scratch (no allocations allowed) ----------------
__device__ float g_resq[BB * HH];          // 128 KB
__device__ float g_logit[BB * LL];         // 256 KB (compacted logits)
__device__ float g_weights[BB * LL];       // 256 KB (full, scattered)
__device__ float g_wcmp[BB * LL];          // 256 KB (compacted weights)
__device__ float g_part[BB * 32 * CC];     // 2 MB
__device__ __half g_wc_h[HH * CC];         // 1 MB  (Wc in fp16, [h][k])
__device__ int   g_idx[BB * LL];           // compacted row indices
__device__ int   g_cnt[BB];                // unmasked count per batch

// ---------------- helpers ----------------
__device__ __forceinline__ uint32_t smem_u32(const void* p) {
    uint32_t a;
    asm("{ .reg .u64 t; cvta.to.shared.u64 t, %1; cvt.u32.u64 %0, t; }"
        : "=r"(a) : "l"(p));
    return a;
}

__device__ __forceinline__ void ldsm4(uint32_t& r0, uint32_t& r1,
                                      uint32_t& r2, uint32_t& r3, uint32_t addr) {
    asm volatile("ldmatrix.sync.aligned.m8n8.x4.shared.b16 {%0,%1,%2,%3}, [%4];"
                 : "=r"(r0), "=r"(r1), "=r"(r2), "=r"(r3) : "r"(addr));
}

__device__ __forceinline__ void mma16816(float* c,
                                         uint32_t a0, uint32_t a1, uint32_t a2, uint32_t a3,
                                         uint32_t b0, uint32_t b1) {
    asm volatile(
        "mma.sync.aligned.m16n8k16.row.col.f32.f16.f16.f32 "
        "{%0,%1,%2,%3}, {%4,%5,%6,%7}, {%8,%9}, {%0,%1,%2,%3};"
        : "+f"(c[0]), "+f"(c[1]), "+f"(c[2]), "+f"(c[3])
        : "r"(a0), "r"(a1), "r"(a2), "r"(a3), "r"(b0), "r"(b1));
}

__device__ __forceinline__ void cp_async16(uint32_t dst, const void* src) {
    asm volatile("cp.async.cg.shared.global [%0], [%1], 16;" :: "r"(dst), "l"(src));
}
#define CP_COMMIT() asm volatile("cp.async.commit_group;" ::: "memory")
#define CP_WAIT0()  asm volatile("cp.async.wait_group 0;" ::: "memory")

// MUFU-pipe tanh: 2 MUFU + ~4 FMA. Overlaps with tensor/FMA pipes.
__device__ __forceinline__ float tanh_mufu(float x) {
    float t = __expf(2.0f * x);                  // ex2.approx path
    return 1.0f - __fdividef(2.0f, t + 1.0f);    // rcp.approx path
}

// ---------------- kernel 0: Wc -> fp16 ----------------
__global__ void wcprep_kernel(const float* __restrict__ Wc) {
    const int i = blockIdx.x * 256 + threadIdx.x;    // 131072 float4s
    float4 v = reinterpret_cast<const float4*>(Wc)[i];
    __half2 h0 = __floats2half2_rn(v.x, v.y);
    __half2 h1 = __floats2half2_rn(v.z, v.w);
    uint2 u;
    u.x = *reinterpret_cast<uint32_t*>(&h0);
    u.y = *reinterpret_cast<uint32_t*>(&h1);
    reinterpret_cast<uint2*>(g_wc_h)[i] = u;
}

// ---------------- kernel 1: res_q = query @ Wq^T ----------------
__global__ void resq_kernel(const float* __restrict__ query,
                            const float* __restrict__ Wq) {
    __shared__ float q[QQ];
    const int b = blockIdx.x, t = threadIdx.x;
    for (int i = t; i < QQ; i += 256) q[i] = query[b * QQ + i];
    __syncthreads();
#pragma unroll
    for (int j = 0; j < 4; j++) {
        const int h = t + j * 256;
        const float4* w = (const float4*)(Wq + (size_t)h * QQ);
        float acc = 0.f;
#pragma unroll 8
        for (int c4 = 0; c4 < QQ / 4; c4++) {
            float4 wv = w[c4];
            acc += wv.x * q[c4 * 4 + 0] + wv.y * q[c4 * 4 + 1]
                 + wv.z * q[c4 * 4 + 2] + wv.w * q[c4 * 4 + 3];
        }
        g_resq[b * HH + h] = acc;
    }
}

// ---------------- kernel 1b: stable compaction of unmasked rows ----------
__global__ void compact_kernel(const float* __restrict__ mask) {
    __shared__ int s[256];
    __shared__ int sbase;
    const int b = blockIdx.x, t = threadIdx.x;
    if (t == 0) sbase = 0;
    for (int ch = 0; ch < 8; ch++) {
        const int l = ch * 256 + t;
        const int flag = (mask[b * LL + l] != 0.0f) ? 1 : 0;
        __syncthreads();                  // protect s[] reuse + sbase update
        s[t] = flag;
        __syncthreads();
#pragma unroll
        for (int off = 1; off < 256; off <<= 1) {
            const int u = (t >= off) ? s[t - off] : 0;
            __syncthreads();
            s[t] += u;
            __syncthreads();
        }
        const int pos = sbase + s[t] - flag;     // exclusive prefix
        if (flag) g_idx[b * LL + pos] = l;
        __syncthreads();
        if (t == 0) sbase += s[255];
    }
    __syncthreads();
    if (t == 0) g_cnt[b] = sbase;
}

// ---------------- kernel 2: mma.sync fused GEMM + tanh + Wo-reduce ----------
// Runs ONLY on compacted (unmasked) rows. CTA = 64 compacted rows of batch b.
// A gathered via g_idx (rows are 2KB contiguous -> coalesced). Occupancy 2.
// N=1024 in 8 tiles of 128; K=512 in 8 chunks -> 64 iterations, 1 barrier each.
// Warps 2Mx4N (32M x 32N tiles). B dbl-buffered via cp.async.
#define A_SZ    65536                 // 64 x 512 fp16
#define B_SZ    16384                 // 128 x 64 fp16
#define RQ_OFF  (A_SZ + 2 * B_SZ)     // 98304
#define WO_OFF  (RQ_OFF + 4096)
#define RED_OFF (WO_OFF + 4096)
#define SM_REQ  (RED_OFF + 768 + 128)

__global__ __launch_bounds__(256, 2) void logits_mma_kernel(
    const float* __restrict__ ctx, const float* __restrict__ bc,
    const float* __restrict__ Wo, const float* __restrict__ bo) {
    const int b = blockIdx.x >> 5;            // 32 tile slots per batch
    const int m0 = (blockIdx.x & 31) * 64;
    const int cnt = g_cnt[b];
    if (m0 >= cnt) return;

    extern __shared__ char smraw[];
    __shared__ int rid_s[64];
    const uint32_t sb_raw = smem_u32(smraw);
    const uint32_t sb = (sb_raw + 127u) & ~127u;
    char* sm = smraw + (sb - sb_raw);

    const int t = threadIdx.x;
    const int lane = t & 31, warp = t >> 5;
    const int mg = warp >> 2;                 // 0..1: M group (32 rows)
    const int ng = warp & 3;                  // 0..3: N group (32 cols)

    float* rqs_s = (float*)(sm + RQ_OFF);
    float* wos_s = (float*)(sm + WO_OFF);
    float* red_s = (float*)(sm + RED_OFF);
#pragma unroll
    for (int i = 0; i < 4; i++) {
        const int n = t + i * 256;
        rqs_s[n] = g_resq[b * HH + n] + bc[n];
        wos_s[n] = Wo[n];
    }
    if (t < 64) {
        const int rsel = min(m0 + t, cnt - 1);   // pad with last valid row
        rid_s[t] = g_idx[b * LL + rsel];
    }
    __syncthreads();

    // ---- fill A: gathered ctx rows -> fp16 swizzled ----
#pragma unroll 4
    for (int i = 0; i < 16; i++) {
        const int idx = t + i * 256;
        const int row = idx >> 6, c = idx & 63;
        const float4* s = (const float4*)(ctx + ((size_t)b * LL + rid_s[row]) * CC + c * 8);
        float4 v0 = s[0], v1 = s[1];
        __half2 h0 = __floats2half2_rn(v0.x, v0.y);
        __half2 h1 = __floats2half2_rn(v0.z, v0.w);
        __half2 h2 = __floats2half2_rn(v1.x, v1.y);
        __half2 h3 = __floats2half2_rn(v1.z, v1.w);
        uint4 u;
        u.x = *reinterpret_cast<uint32_t*>(&h0);
        u.y = *reinterpret_cast<uint32_t*>(&h1);
        u.z = *reinterpret_cast<uint32_t*>(&h2);
        u.w = *reinterpret_cast<uint32_t*>(&h3);
        *(uint4*)(sm + row * 1024 + (((c ^ (row & 7))) << 4)) = u;
    }

    const uint32_t sb_B = sb + A_SZ;

    auto fill_B = [&](int buf, int it) {
        const int ntv = it >> 3, kkv = it & 7;
#pragma unroll
        for (int i = 0; i < 4; i++) {
            const int idx = t + i * 256;
            const int row = idx >> 3, c = idx & 7;
            const __half* src = g_wc_h + (size_t)(ntv * 128 + row) * CC + kkv * 64 + c * 8;
            const uint32_t dst = sb_B + buf * B_SZ + row * 128 + (((c ^ (row & 7))) << 4);
            cp_async16(dst, src);
        }
        CP_COMMIT();
    };

    fill_B(0, 0);

    const uint32_t a_row_addr = sb + (mg * 32 + (lane & 15)) * 1024;
    const int a_hi = lane >> 4;
    const int asw = lane & 7;
    const int brow = (lane & 7) + ((lane & 16) >> 1);
    const int bkbit = (lane >> 3) & 1;
    const int bsw = lane & 7;

    float p[4] = {0.f, 0.f, 0.f, 0.f};
    const float bo0 = bo[0];

    float acc[2][4][4];
    for (int it = 0; it < 64; it++) {
        const int nt = it >> 3, kk = it & 7;
        if (kk == 0) {
#pragma unroll
            for (int mt = 0; mt < 2; mt++)
#pragma unroll
                for (int nb = 0; nb < 4; nb++)
#pragma unroll
                    for (int j = 0; j < 4; j++) acc[mt][nb][j] = 0.f;
        }

        CP_WAIT0();
        __syncthreads();
        if (it + 1 < 64) fill_B((it + 1) & 1, it + 1);

        const uint32_t bbase = sb_B + (uint32_t)(it & 1) * B_SZ + (uint32_t)ng * 32 * 128;
#pragma unroll
        for (int ks = 0; ks < 4; ks++) {
            uint32_t a[2][4];
            const int c0 = kk * 8 + ks * 2 + a_hi;
            const uint32_t aoff = (uint32_t)(c0 ^ asw) << 4;
            ldsm4(a[0][0], a[0][1], a[0][2], a[0][3], a_row_addr + aoff);
            ldsm4(a[1][0], a[1][1], a[1][2], a[1][3], a_row_addr + 16384 + aoff);
            const int chunk = ks * 2 + bkbit;
            uint32_t bf[2][4];
#pragma unroll
            for (int pq = 0; pq < 2; pq++) {
                const uint32_t baddr = bbase + (uint32_t)(pq * 16 + brow) * 128
                                     + ((uint32_t)(chunk ^ bsw) << 4);
                ldsm4(bf[pq][0], bf[pq][1], bf[pq][2], bf[pq][3], baddr);
            }
#pragma unroll
            for (int mt = 0; mt < 2; mt++)
#pragma unroll
                for (int pq = 0; pq < 2; pq++) {
                    mma16816(acc[mt][2 * pq],     a[mt][0], a[mt][1], a[mt][2], a[mt][3],
                             bf[pq][0], bf[pq][1]);
                    mma16816(acc[mt][2 * pq + 1], a[mt][0], a[mt][1], a[mt][2], a[mt][3],
                             bf[pq][2], bf[pq][3]);
                }
        }

        if (kk == 7) {
#pragma unroll
            for (int mt = 0; mt < 2; mt++)
#pragma unroll
                for (int nb = 0; nb < 4; nb++) {
                    const int ngl = nt * 128 + ng * 32 + nb * 8 + ((lane & 3) << 1);
                    const float rq0 = rqs_s[ngl],     w0 = wos_s[ngl];
                    const float rq1 = rqs_s[ngl + 1], w1 = wos_s[ngl + 1];
                    p[2 * mt]     += w0 * tanh_mufu(acc[mt][nb][0] + rq0);
                    p[2 * mt]     += w1 * tanh_mufu(acc[mt][nb][1] + rq1);
                    p[2 * mt + 1] += w0 * tanh_mufu(acc[mt][nb][2] + rq0);
                    p[2 * mt + 1] += w1 * tanh_mufu(acc[mt][nb][3] + rq1);
                }
        }
    }

#pragma unroll
    for (int j = 0; j < 4; j++) {
        p[j] += __shfl_xor_sync(0xffffffffu, p[j], 1);
        p[j] += __shfl_xor_sync(0xffffffffu, p[j], 2);
    }
    if (ng > 0 && (lane & 3) == 0) {
        float* dst = red_s + (ng - 1) * 64 + mg * 32 + (lane >> 2);
        dst[0]  = p[0];
        dst[8]  = p[1];
        dst[16] = p[2];
        dst[24] = p[3];
    }
    __syncthreads();
    if (ng == 0 && (lane & 3) == 0) {
        const int r = mg * 32 + (lane >> 2);
#pragma unroll
        for (int j = 0; j < 4; j++) {
            const int row = r + 8 * j;
            if (m0 + row < cnt)
                g_logit[b * LL + m0 + row] = p[j] + red_s[row] + red_s[64 + row]
                                           + red_s[128 + row] + bo0;
        }
    }
}

// ---------------- kernel 3: masked exp + normalize (compacted) -------------
__global__ void softmax_kernel(const float* __restrict__ mask,
                               float* __restrict__ w_out, int write_w) {
    __shared__ float sred[256];
    const int b = blockIdx.x, t = threadIdx.x;
    const int cnt = g_cnt[b];
    // zero full (scattered) weights first
    for (int i = t; i < LL; i += 256) {
        g_weights[b * LL + i] = 0.f;
        if (write_w) w_out[b * LL + i] = 0.f;
    }
    float e[8];
    int ids[8];
    float s = 0.f;
#pragma unroll
    for (int i = 0; i < 8; i++) {
        const int j = t + i * 256;
        float ev = 0.f;
        int id = -1;
        if (j < cnt) {
            id = g_idx[b * LL + j];
            ev = mask[b * LL + id] * expf(g_logit[b * LL + j]);
        }
        e[i] = ev;
        ids[i] = id;
        s += ev;
    }
    sred[t] = s;
    __syncthreads();
#pragma unroll
    for (int off = 128; off > 0; off >>= 1) {
        if (t < off) sred[t] += sred[t + off];
        __syncthreads();
    }
    const float inv = 1.f / (sred[0] + 1e-5f);
#pragma unroll
    for (int i = 0; i < 8; i++) {
        if (ids[i] >= 0) {
            const float wv = e[i] * inv;
            g_wcmp[b * LL + t + i * 256] = wv;       // compact (for wsum)
            g_weights[b * LL + ids[i]] = wv;         // scattered
            if (write_w) w_out[b * LL + ids[i]] = wv;
        }
    }
}

// ---------------- kernel 4: weighted sum over compacted rows --------------
__global__ void wsum_kernel(const float* __restrict__ ctx) {
    const int b = blockIdx.x, seg = blockIdx.y, t = threadIdx.x;
    const int cnt = g_cnt[b];
    float* dst = g_part + (size_t)(b * 32 + seg) * CC;
    if (seg * 64 >= cnt) {                 // inactive segment: zero partials
        dst[t * 2] = 0.f;
        dst[t * 2 + 1] = 0.f;
        return;
    }
    __shared__ float ws[64];
    __shared__ int wi[64];
    if (t < 64) {
        const int j = seg * 64 + t;
        if (j < cnt) { ws[t] = g_wcmp[b * LL + j]; wi[t] = g_idx[b * LL + j]; }
        else         { ws[t] = 0.f;                wi[t] = 0; }
    }
    __syncthreads();
    const int nrows = min(64, cnt - seg * 64);
    float ax = 0.f, ay = 0.f;
#pragma unroll 4
    for (int li = 0; li < nrows; li++) {
        const float2 v = ((const float2*)(ctx + ((size_t)b * LL + wi[li]) * CC))[t];
        const float w = ws[li];
        ax += w * v.x;
        ay += w * v.y;
    }
    dst[t * 2] = ax;
    dst[t * 2 + 1] = ay;
}

__global__ void reduce_kernel(float* __restrict__ out_vec) {
    const int idx = blockIdx.x * 256 + threadIdx.x;  // 0..16383
    const int b = idx >> 9, c = idx & 511;
    float s = 0.f;
#pragma unroll
    for (int ls = 0; ls < 32; ls++) s += g_part[(size_t)(b * 32 + ls) * CC + c];
    out_vec[b * CC + c] = s;
}

// ---------------- launch ----------------
extern "C" void kernel_launch(void* const* d_in, const int* in_sizes, int n_in,
                              void* d_out, int out_size) {
    const float* query   = (const float*)d_in[0];
    const float* context = (const float*)d_in[1];
    const float* mask    = (const float*)d_in[2];
    const float* Wq      = (const float*)d_in[3];
    const float* Wc      = (const float*)d_in[4];
    const float* bc      = (const float*)d_in[5];
    const float* Wo      = (const float*)d_in[6];
    const float* bo      = (const float*)d_in[7];

    float* out = (float*)d_out;
    float* out_vec = nullptr;
    float* out_w = nullptr;
    if (out_size >= BB * CC + BB * LL) {
        out_vec = out;
        out_w = out + BB * CC;
    } else if (out_size == BB * LL) {
        out_w = out;
    } else {
        out_vec = out;
    }

    cudaFuncSetAttribute(logits_mma_kernel,
                         cudaFuncAttributeMaxDynamicSharedMemorySize, SM_REQ);

    wcprep_kernel<<<512, 256>>>(Wc);
    resq_kernel<<<BB, 256>>>(query, Wq);
    compact_kernel<<<BB, 256>>>(mask);
    logits_mma_kernel<<<(BB * LL) / 64, 256, SM_REQ>>>(context, bc, Wo, bo);
    softmax_kernel<<<BB, 256>>>(mask, out_w, out_w != nullptr ? 1 : 0);
    wsum_kernel<<<dim3(BB, 32), 256>>>(context);
    if (out_vec) reduce_kernel<<<(BB * CC) / 256, 256>>>(out_vec);
}

// round 8
// speedup vs baseline: 10.3879x; 1.3120x over previous
#include <cuda_runtime.h>
#include <cuda_fp16.h>
#include <cstdint>

#define BB 32
#define LL 2048
#define CC 512
#define QQ 512
#define HH 1024

// ---------------- scratch (no allocations allowed) ----------------
__device__ float g_resq[BB * HH];          // 128 KB
__device__ float g_logit[BB * LL];         // 256 KB (compacted logits)
__device__ float g_weights[BB * LL];       // 256 KB (full, scattered)
__device__ float g_wcmp[BB * LL];          // 256 KB (compacted weights)
__device__ float g_part[BB * 32 * CC];     // 2 MB
__device__ __half g_wc_h[HH * CC];         // 1 MB  (Wc in fp16, [h][k])
__device__ int   g_idx[BB * LL];           // compacted row indices
__device__ int   g_cnt[BB];                // unmasked count per batch

// ---------------- helpers ----------------
__device__ __forceinline__ uint32_t smem_u32(const void* p) {
    uint32_t a;
    asm("{ .reg .u64 t; cvta.to.shared.u64 t, %1; cvt.u32.u64 %0, t; }"
        : "=r"(a) : "l"(p));
    return a;
}

__device__ __forceinline__ void ldsm4(uint32_t& r0, uint32_t& r1,
                                      uint32_t& r2, uint32_t& r3, uint32_t addr) {
    asm volatile("ldmatrix.sync.aligned.m8n8.x4.shared.b16 {%0,%1,%2,%3}, [%4];"
                 : "=r"(r0), "=r"(r1), "=r"(r2), "=r"(r3) : "r"(addr));
}

__device__ __forceinline__ void mma16816(float* c,
                                         uint32_t a0, uint32_t a1, uint32_t a2, uint32_t a3,
                                         uint32_t b0, uint32_t b1) {
    asm volatile(
        "mma.sync.aligned.m16n8k16.row.col.f32.f16.f16.f32 "
        "{%0,%1,%2,%3}, {%4,%5,%6,%7}, {%8,%9}, {%0,%1,%2,%3};"
        : "+f"(c[0]), "+f"(c[1]), "+f"(c[2]), "+f"(c[3])
        : "r"(a0), "r"(a1), "r"(a2), "r"(a3), "r"(b0), "r"(b1));
}

__device__ __forceinline__ void cp_async16(uint32_t dst, const void* src) {
    asm volatile("cp.async.cg.shared.global [%0], [%1], 16;" :: "r"(dst), "l"(src));
}
#define CP_COMMIT() asm volatile("cp.async.commit_group;" ::: "memory")
#define CP_WAIT0()  asm volatile("cp.async.wait_group 0;" ::: "memory")

// MUFU-pipe tanh: 2 MUFU + ~4 FMA. Overlaps with tensor pipe.
__device__ __forceinline__ float tanh_mufu(float x) {
    float t = __expf(2.0f * x);
    return 1.0f - __fdividef(2.0f, t + 1.0f);
}

// ---------------- kernel P: merged prep (wcprep | resq | compact) ----------
// blocks [0,512): Wc -> fp16
// blocks [512,640): res_q = query @ Wq^T   (4 blocks per batch)
// blocks [640,672): stable compaction of unmasked rows (1 block per batch)
__global__ __launch_bounds__(256) void prep_kernel(
    const float* __restrict__ Wc, const float* __restrict__ query,
    const float* __restrict__ Wq, const float* __restrict__ mask) {
    const int blk = blockIdx.x;
    const int t = threadIdx.x;

    if (blk < 512) {                       // ---- Wc -> fp16 ----
        const int i = blk * 256 + t;
        float4 v = reinterpret_cast<const float4*>(Wc)[i];
        __half2 h0 = __floats2half2_rn(v.x, v.y);
        __half2 h1 = __floats2half2_rn(v.z, v.w);
        uint2 u;
        u.x = *reinterpret_cast<uint32_t*>(&h0);
        u.y = *reinterpret_cast<uint32_t*>(&h1);
        reinterpret_cast<uint2*>(g_wc_h)[i] = u;
        return;
    }

    if (blk < 640) {                       // ---- res_q ----
        __shared__ float q[QQ];
        const int rb = blk - 512;
        const int b = rb >> 2, part = rb & 3;
        for (int i = t; i < QQ; i += 256) q[i] = query[b * QQ + i];
        __syncthreads();
        const int h = part * 256 + t;
        const float4* w = (const float4*)(Wq + (size_t)h * QQ);
        float acc = 0.f;
#pragma unroll 8
        for (int c4 = 0; c4 < QQ / 4; c4++) {
            float4 wv = w[c4];
            acc += wv.x * q[c4 * 4 + 0] + wv.y * q[c4 * 4 + 1]
                 + wv.z * q[c4 * 4 + 2] + wv.w * q[c4 * 4 + 3];
        }
        g_resq[b * HH + h] = acc;
        return;
    }

    // ---- compaction (ballot-based, stable) ----
    {
        __shared__ int warpsum[8];
        __shared__ int sbase;
        const int b = blk - 640;
        const int lane = t & 31, warp = t >> 5;
        if (t == 0) sbase = 0;
        __syncthreads();
        for (int ch = 0; ch < 8; ch++) {
            const int l = ch * 256 + t;
            const int flag = (mask[b * LL + l] != 0.0f) ? 1 : 0;
            const uint32_t bal = __ballot_sync(0xffffffffu, flag);
            const int wpre = __popc(bal & ((1u << lane) - 1u));
            if (lane == 0) warpsum[warp] = __popc(bal);
            __syncthreads();
            int base = 0, ctot = 0;
#pragma unroll
            for (int w = 0; w < 8; w++) {
                base += (w < warp) ? warpsum[w] : 0;
                ctot += warpsum[w];
            }
            if (flag) g_idx[b * LL + sbase + base + wpre] = l;
            __syncthreads();
            if (t == 0) sbase += ctot;
            __syncthreads();
        }
        if (t == 0) g_cnt[b] = sbase;
    }
}

// ---------------- kernel 2: mma.sync fused GEMM + tanh + Wo-reduce ----------
// Compacted rows only. CTA = 64 rows. Occupancy 2. Warps 2Mx4N (32Mx32N).
// All swizzle math strength-reduced to per-lane constants.
#define A_SZ    65536                 // 64 x 512 fp16
#define B_SZ    16384                 // 128 x 64 fp16
#define RQ_OFF  (A_SZ + 2 * B_SZ)     // 98304
#define WO_OFF  (RQ_OFF + 4096)
#define RED_OFF (WO_OFF + 4096)
#define SM_REQ  (RED_OFF + 768 + 128)

__global__ __launch_bounds__(256, 2) void logits_mma_kernel(
    const float* __restrict__ ctx, const float* __restrict__ bc,
    const float* __restrict__ Wo, const float* __restrict__ bo) {
    const int b = blockIdx.x >> 5;
    const int m0 = (blockIdx.x & 31) * 64;
    const int cnt = g_cnt[b];
    if (m0 >= cnt) return;

    extern __shared__ char smraw[];
    __shared__ int rid_s[64];
    const uint32_t sb_raw = smem_u32(smraw);
    const uint32_t sb = (sb_raw + 127u) & ~127u;
    char* sm = smraw + (sb - sb_raw);

    const int t = threadIdx.x;
    const int lane = t & 31, warp = t >> 5;
    const int mg = warp >> 2;
    const int ng = warp & 3;

    float* rqs_s = (float*)(sm + RQ_OFF);
    float* wos_s = (float*)(sm + WO_OFF);
    float* red_s = (float*)(sm + RED_OFF);
#pragma unroll
    for (int i = 0; i < 4; i++) {
        const int n = t + i * 256;
        rqs_s[n] = g_resq[b * HH + n] + bc[n];
        wos_s[n] = Wo[n];
    }
    if (t < 64) {
        const int rsel = min(m0 + t, cnt - 1);
        rid_s[t] = g_idx[b * LL + rsel];
    }
    __syncthreads();

    // ---- fill A: gathered ctx rows -> fp16 swizzled ----
#pragma unroll 4
    for (int i = 0; i < 16; i++) {
        const int idx = t + i * 256;
        const int row = idx >> 6, c = idx & 63;
        const float4* s = (const float4*)(ctx + ((size_t)b * LL + rid_s[row]) * CC + c * 8);
        float4 v0 = s[0], v1 = s[1];
        __half2 h0 = __floats2half2_rn(v0.x, v0.y);
        __half2 h1 = __floats2half2_rn(v0.z, v0.w);
        __half2 h2 = __floats2half2_rn(v1.x, v1.y);
        __half2 h3 = __floats2half2_rn(v1.z, v1.w);
        uint4 u;
        u.x = *reinterpret_cast<uint32_t*>(&h0);
        u.y = *reinterpret_cast<uint32_t*>(&h1);
        u.z = *reinterpret_cast<uint32_t*>(&h2);
        u.w = *reinterpret_cast<uint32_t*>(&h3);
        *(uint4*)(sm + row * 1024 + (((c ^ (row & 7))) << 4)) = u;
    }

    const uint32_t sb_B = sb + A_SZ;

    // ---- strength-reduced fill_B constants ----
    const int fc = t & 7;                 // 16B chunk within 64k
    const int frow0 = t >> 3;             // first of 4 rows (stride 32)
    uint32_t fdst[4];
    const __half* fsrc[4];
#pragma unroll
    for (int i = 0; i < 4; i++) {
        const int row = frow0 + i * 32;
        fdst[i] = sb_B + (uint32_t)(row * 128 + ((fc ^ (row & 7)) << 4));
        fsrc[i] = g_wc_h + (size_t)row * CC + fc * 8;
    }

    auto fill_B = [&](uint32_t bufoff, int it) {
        const int goff = ((it >> 3) << 16) + ((it & 7) << 6);  // ntv*128*512 + kkv*64
#pragma unroll
        for (int i = 0; i < 4; i++)
            cp_async16(fdst[i] + bufoff, fsrc[i] + goff);
        CP_COMMIT();
    };

    fill_B(0, 0);

    // ---- strength-reduced LDSM constants ----
    // A: (kk*8 + ks*2 + a_hi) ^ asw == kk*8 + ((ks*2+a_hi)^asw)  (low-3-bit XOR)
    const uint32_t a_row_addr = sb + (mg * 32 + (lane & 15)) * 1024;
    const int a_hi = lane >> 4;
    const int asw = lane & 7;
    uint32_t aoffC[4];
#pragma unroll
    for (int ks = 0; ks < 4; ks++)
        aoffC[ks] = (uint32_t)(((ks * 2 + a_hi) ^ asw) << 4);

    const int brow = (lane & 7) + ((lane & 16) >> 1);
    const int bkbit = (lane >> 3) & 1;
    const int bsw = lane & 7;
    uint32_t boffC[4];
#pragma unroll
    for (int ks = 0; ks < 4; ks++)
        boffC[ks] = (uint32_t)(((ks * 2 + bkbit) ^ bsw) << 4);
    const uint32_t bbase0 = sb_B + (uint32_t)ng * 32 * 128 + (uint32_t)(brow << 7);
    const uint32_t bbase1 = bbase0 + B_SZ;
    const uint32_t browoff1 = 16u << 7;      // pq=1: +16 rows

    float p[4] = {0.f, 0.f, 0.f, 0.f};
    const float bo0 = bo[0];

    for (int nt = 0; nt < 8; nt++) {
        float acc[2][4][4];
#pragma unroll
        for (int mt = 0; mt < 2; mt++)
#pragma unroll
            for (int nb = 0; nb < 4; nb++)
#pragma unroll
                for (int j = 0; j < 4; j++) acc[mt][nb][j] = 0.f;

        for (int kk = 0; kk < 8; kk++) {
            const int it = nt * 8 + kk;
            CP_WAIT0();
            __syncthreads();
            if (it + 1 < 64) fill_B(((it + 1) & 1) ? B_SZ : 0u, it + 1);

            const uint32_t bb = (it & 1) ? bbase1 : bbase0;
            const uint32_t arow = a_row_addr + ((uint32_t)kk << 7);
#pragma unroll
            for (int ks = 0; ks < 4; ks++) {
                uint32_t a[2][4];
                ldsm4(a[0][0], a[0][1], a[0][2], a[0][3], arow + aoffC[ks]);
                ldsm4(a[1][0], a[1][1], a[1][2], a[1][3], arow + 16384 + aoffC[ks]);
                uint32_t bf[2][4];
                ldsm4(bf[0][0], bf[0][1], bf[0][2], bf[0][3], bb + boffC[ks]);
                ldsm4(bf[1][0], bf[1][1], bf[1][2], bf[1][3], bb + browoff1 + boffC[ks]);
#pragma unroll
                for (int mt = 0; mt < 2; mt++)
#pragma unroll
                    for (int pq = 0; pq < 2; pq++) {
                        mma16816(acc[mt][2 * pq],     a[mt][0], a[mt][1], a[mt][2], a[mt][3],
                                 bf[pq][0], bf[pq][1]);
                        mma16816(acc[mt][2 * pq + 1], a[mt][0], a[mt][1], a[mt][2], a[mt][3],
                                 bf[pq][2], bf[pq][3]);
                    }
            }
        }

        // ---- fused epilogue for n-tile nt ----
#pragma unroll
        for (int mt = 0; mt < 2; mt++)
#pragma unroll
            for (int nb = 0; nb < 4; nb++) {
                const int ngl = nt * 128 + ng * 32 + nb * 8 + ((lane & 3) << 1);
                const float rq0 = rqs_s[ngl],     w0 = wos_s[ngl];
                const float rq1 = rqs_s[ngl + 1], w1 = wos_s[ngl + 1];
                p[2 * mt]     += w0 * tanh_mufu(acc[mt][nb][0] + rq0);
                p[2 * mt]     += w1 * tanh_mufu(acc[mt][nb][1] + rq1);
                p[2 * mt + 1] += w0 * tanh_mufu(acc[mt][nb][2] + rq0);
                p[2 * mt + 1] += w1 * tanh_mufu(acc[mt][nb][3] + rq1);
            }
    }

#pragma unroll
    for (int j = 0; j < 4; j++) {
        p[j] += __shfl_xor_sync(0xffffffffu, p[j], 1);
        p[j] += __shfl_xor_sync(0xffffffffu, p[j], 2);
    }
    if (ng > 0 && (lane & 3) == 0) {
        float* dst = red_s + (ng - 1) * 64 + mg * 32 + (lane >> 2);
        dst[0]  = p[0];
        dst[8]  = p[1];
        dst[16] = p[2];
        dst[24] = p[3];
    }
    __syncthreads();
    if (ng == 0 && (lane & 3) == 0) {
        const int r = mg * 32 + (lane >> 2);
#pragma unroll
        for (int j = 0; j < 4; j++) {
            const int row = r + 8 * j;
            if (m0 + row < cnt)
                g_logit[b * LL + m0 + row] = p[j] + red_s[row] + red_s[64 + row]
                                           + red_s[128 + row] + bo0;
        }
    }
}

// ---------------- kernel 3: masked exp + normalize (compacted) -------------
__global__ void softmax_kernel(const float* __restrict__ mask,
                               float* __restrict__ w_out, int write_w) {
    __shared__ float sred[256];
    const int b = blockIdx.x, t = threadIdx.x;
    const int cnt = g_cnt[b];
    for (int i = t; i < LL; i += 256) {
        g_weights[b * LL + i] = 0.f;
        if (write_w) w_out[b * LL + i] = 0.f;
    }
    float e[8];
    int ids[8];
    float s = 0.f;
#pragma unroll
    for (int i = 0; i < 8; i++) {
        const int j = t + i * 256;
        float ev = 0.f;
        int id = -1;
        if (j < cnt) {
            id = g_idx[b * LL + j];
            ev = mask[b * LL + id] * expf(g_logit[b * LL + j]);
        }
        e[i] = ev;
        ids[i] = id;
        s += ev;
    }
    sred[t] = s;
    __syncthreads();
#pragma unroll
    for (int off = 128; off > 0; off >>= 1) {
        if (t < off) sred[t] += sred[t + off];
        __syncthreads();
    }
    const float inv = 1.f / (sred[0] + 1e-5f);
#pragma unroll
    for (int i = 0; i < 8; i++) {
        if (ids[i] >= 0) {
            const float wv = e[i] * inv;
            g_wcmp[b * LL + t + i * 256] = wv;
            g_weights[b * LL + ids[i]] = wv;
            if (write_w) w_out[b * LL + ids[i]] = wv;
        }
    }
}

// ---------------- kernel 4: weighted sum over compacted rows --------------
__global__ void wsum_kernel(const float* __restrict__ ctx) {
    const int b = blockIdx.x, seg = blockIdx.y, t = threadIdx.x;
    const int cnt = g_cnt[b];
    float* dst = g_part + (size_t)(b * 32 + seg) * CC;
    if (seg * 64 >= cnt) {
        dst[t * 2] = 0.f;
        dst[t * 2 + 1] = 0.f;
        return;
    }
    __shared__ float ws[64];
    __shared__ int wi[64];
    if (t < 64) {
        const int j = seg * 64 + t;
        if (j < cnt) { ws[t] = g_wcmp[b * LL + j]; wi[t] = g_idx[b * LL + j]; }
        else         { ws[t] = 0.f;                wi[t] = 0; }
    }
    __syncthreads();
    const int nrows = min(64, cnt - seg * 64);
    float ax = 0.f, ay = 0.f;
#pragma unroll 4
    for (int li = 0; li < nrows; li++) {
        const float2 v = ((const float2*)(ctx + ((size_t)b * LL + wi[li]) * CC))[t];
        const float w = ws[li];
        ax += w * v.x;
        ay += w * v.y;
    }
    dst[t * 2] = ax;
    dst[t * 2 + 1] = ay;
}

__global__ void reduce_kernel(float* __restrict__ out_vec) {
    const int idx = blockIdx.x * 256 + threadIdx.x;
    const int b = idx >> 9, c = idx & 511;
    float s = 0.f;
#pragma unroll
    for (int ls = 0; ls < 32; ls++) s += g_part[(size_t)(b * 32 + ls) * CC + c];
    out_vec[b * CC + c] = s;
}

// ---------------- launch ----------------
extern "C" void kernel_launch(void* const* d_in, const int* in_sizes, int n_in,
                              void* d_out, int out_size) {
    const float* query   = (const float*)d_in[0];
    const float* context = (const float*)d_in[1];
    const float* mask    = (const float*)d_in[2];
    const float* Wq      = (const float*)d_in[3];
    const float* Wc      = (const float*)d_in[4];
    const float* bc      = (const float*)d_in[5];
    const float* Wo      = (const float*)d_in[6];
    const float* bo      = (const float*)d_in[7];

    float* out = (float*)d_out;
    float* out_vec = nullptr;
    float* out_w = nullptr;
    if (out_size >= BB * CC + BB * LL) {
        out_vec = out;
        out_w = out + BB * CC;
    } else if (out_size == BB * LL) {
        out_w = out;
    } else {
        out_vec = out;
    }

    cudaFuncSetAttribute(logits_mma_kernel,
                         cudaFuncAttributeMaxDynamicSharedMemorySize, SM_REQ);

    prep_kernel<<<672, 256>>>(Wc, query, Wq, mask);
    logits_mma_kernel<<<(BB * LL) / 64, 256, SM_REQ>>>(context, bc, Wo, bo);
    softmax_kernel<<<BB, 256>>>(mask, out_w, out_w != nullptr ? 1 : 0);
    wsum_kernel<<<dim3(BB, 32), 256>>>(context);
    if (out_vec) reduce_kernel<<<(BB * CC) / 256, 256>>>(out_vec);
}